// round 17
// baseline (speedup 1.0000x reference)
#include <cuda_runtime.h>
#include <cuda_bf16.h>
#include <cuda_fp16.h>
#include <math_constants.h>
#include <cstdint>

#define B_ 2
#define T_ 2048
#define C_ 2048
#define H_ 16
#define D_ 128
#define M_ (B_*T_)   // 4096 rows

// ---------------- scratch (static device globals) ----------------
__device__ __half g_xf[(size_t)M_ * C_];
__device__ __half g_qf[(size_t)M_ * C_];
__device__ __half g_kf[(size_t)M_ * C_];
__device__ __half g_vf[(size_t)M_ * C_];
__device__ __half g_of[(size_t)M_ * C_];
__device__ __half g_wf[4][(size_t)C_ * C_];   // Wq, Wk, Wv, Wo fp16

union HU { __half2 h; uint32_t u; };

__device__ __forceinline__ uint32_t pack_f16(float x, float y) {
    HU u; u.h = __floats2half2_rn(x, y); return u.u;
}

// ---------------------------------------------------------------------------
// split kernel: x, W0..W3 -> fp16. 4 float4 per thread for MLP.
// ---------------------------------------------------------------------------
#define NX4 ((M_*C_)/4)
#define NW4 ((C_*C_)/4)
#define NTOT4 (NX4 + 4*NW4)

__global__ __launch_bounds__(512) void split_all(
    const float4* __restrict__ x,
    const float4* __restrict__ w0, const float4* __restrict__ w1,
    const float4* __restrict__ w2, const float4* __restrict__ w3,
    uint2* __restrict__ xf, uint2* __restrict__ wf)
{
    int base = (blockIdx.x * blockDim.x + threadIdx.x) * 4;
    float4 v[4];
    uint2* dsts[4];
    int offs[4];
    #pragma unroll
    for (int e = 0; e < 4; e++) {
        int i = base + e;
        const float4* src;
        uint2* dst;
        int off;
        if (i < NX4) { src = x; off = i; dst = xf; }
        else {
            int j = i - NX4;
            int w = j >> 20;             // NW4 = 2^20
            off = j & (NW4 - 1);
            src = (w == 0) ? w0 : (w == 1) ? w1 : (w == 2) ? w2 : w3;
            dst = wf + (size_t)w * NW4;
        }
        v[e] = src[off];
        dsts[e] = dst; offs[e] = off;
    }
    #pragma unroll
    for (int e = 0; e < 4; e++)
        dsts[e][offs[e]] = make_uint2(pack_f16(v[e].x, v[e].y), pack_f16(v[e].z, v[e].w));
}

// ---------------------------------------------------------------------------
// primitives
// ---------------------------------------------------------------------------
__device__ __forceinline__ void ldmx4(uint32_t &r0, uint32_t &r1, uint32_t &r2, uint32_t &r3, uint32_t addr) {
    asm volatile("ldmatrix.sync.aligned.m8n8.x4.shared.b16 {%0,%1,%2,%3}, [%4];"
                 : "=r"(r0), "=r"(r1), "=r"(r2), "=r"(r3) : "r"(addr));
}
__device__ __forceinline__ void ldmx4t(uint32_t &r0, uint32_t &r1, uint32_t &r2, uint32_t &r3, uint32_t addr) {
    asm volatile("ldmatrix.sync.aligned.m8n8.x4.trans.shared.b16 {%0,%1,%2,%3}, [%4];"
                 : "=r"(r0), "=r"(r1), "=r"(r2), "=r"(r3) : "r"(addr));
}
__device__ __forceinline__ void mmah16(float* d, const uint32_t* a, const uint32_t* b) {
    asm volatile("mma.sync.aligned.m16n8k16.row.col.f32.f16.f16.f32 "
                 "{%0,%1,%2,%3},{%4,%5,%6,%7},{%8,%9},{%0,%1,%2,%3};"
                 : "+f"(d[0]), "+f"(d[1]), "+f"(d[2]), "+f"(d[3])
                 : "r"(a[0]), "r"(a[1]), "r"(a[2]), "r"(a[3]), "r"(b[0]), "r"(b[1]));
}
__device__ __forceinline__ void cp16(uint32_t saddr, const void* g) {
    asm volatile("cp.async.cg.shared.global [%0], [%1], 16;" :: "r"(saddr), "l"(g));
}
__device__ __forceinline__ uint32_t swz128(uint32_t off) { return off ^ ((off >> 3) & 0x70); }

// ---------------------------------------------------------------------------
// fp16 GEMM geometry: 64x128 CTA tile, BK=64, 8 warps (32x32 warp tiles),
// 3 stages, 3 CTAs/SM (24 warps).
// ---------------------------------------------------------------------------
#define G_ASUB 8192
#define G_STAGE 24576
#define G_SMEM (3*G_STAGE)               // 73728 B
#define FTS 133

#define HG2_STAGE_BODY(st)                                                            \
    _Pragma("unroll")                                                                 \
    for (int kk = 0; kk < 64; kk += 16) {                                             \
        uint32_t a[2][4], b[4][2];                                                    \
        _Pragma("unroll")                                                             \
        for (int t = 0; t < 2; t++) {                                                 \
            uint32_t rb = (uint32_t)((warp_m * 32 + t * 16 + mlane) * 128 + (kk + aoff) * 2); \
            ldmx4(a[t][0], a[t][1], a[t][2], a[t][3], (st) + swz128(rb));             \
        }                                                                             \
        _Pragma("unroll")                                                             \
        for (int jt = 0; jt < 2; jt++) {                                              \
            uint32_t rb = (uint32_t)((warp_n * 32 + jt * 16 + nlane) * 128 + (kk + klBo) * 2); \
            ldmx4(b[2*jt][0], b[2*jt][1], b[2*jt+1][0], b[2*jt+1][1], (st) + G_ASUB + swz128(rb)); \
        }                                                                             \
        _Pragma("unroll")                                                             \
        for (int t = 0; t < 2; t++)                                                   \
            _Pragma("unroll")                                                         \
            for (int j = 0; j < 4; j++) mmah16(acc[t][j], a[t], b[j]);                \
    }

// ---------------------------------------------------------------------------
// Fused QKV fp16 GEMM + (rmsnorm+RoPE | passthrough) epilogue.
// grid (48, 64). Q output PRE-SCALED by 1/sqrt(D).
// ---------------------------------------------------------------------------
__global__ __launch_bounds__(256, 3) void qkv_gemm(
    const __half* __restrict__ xf, const __half* __restrict__ wf,
    const float* __restrict__ cs, const float* __restrict__ sn,
    __half* __restrict__ qf, __half* __restrict__ kf, __half* __restrict__ vf)
{
    extern __shared__ __align__(1024) char smg[];
    const int tid = threadIdx.x, lane = tid & 31, wid = tid >> 5;
    const int warp_m = wid & 1;
    const int warp_n = wid >> 1;
    const int bm = blockIdx.y;
    const int kind = blockIdx.x >> 4;
    const int lbn  = blockIdx.x & 15;
    const uint32_t sb = (uint32_t)__cvta_generic_to_shared(smg);

    const __half* Bf = wf + (size_t)kind * C_ * C_;

    float acc[2][4][4];
    #pragma unroll
    for (int i = 0; i < 2; i++)
        #pragma unroll
        for (int j = 0; j < 4; j++)
            #pragma unroll
            for (int e = 0; e < 4; e++) acc[i][j][e] = 0.f;

    auto issue = [&](int s, int k0) {
        const uint32_t st = sb + s * G_STAGE;
        #pragma unroll
        for (int it = 0; it < 6; it++) {
            int idx = tid + it * 256;
            if (idx < 512) {
                int r = idx >> 3, ch = idx & 7;
                cp16(st + swz128((uint32_t)(r * 128 + ch * 16)),
                     xf + (size_t)(bm * 64 + r) * C_ + k0 + ch * 8);
            } else {
                int j = idx - 512;
                int r = j >> 3, ch = j & 7;
                cp16(st + G_ASUB + swz128((uint32_t)(r * 128 + ch * 16)),
                     Bf + (size_t)(lbn * 128 + r) * C_ + k0 + ch * 8);
            }
        }
        asm volatile("cp.async.commit_group;");
    };

    const int NS = C_ / 64;
    issue(0, 0);
    issue(1, 64);

    const int mlane = lane & 15;
    const int aoff  = (lane >> 4) << 3;
    const int nlane = (lane & 7) + ((lane >> 4) << 3);
    const int klBo  = ((lane >> 3) & 1) << 3;

    for (int i = 0; i < NS; i++) {
        if (i == NS - 1) { asm volatile("cp.async.wait_group 0;"); }
        else             { asm volatile("cp.async.wait_group 1;"); }
        __syncthreads();
        if (i + 2 < NS) issue((i + 2) % 3, (i + 2) * 64);

        const uint32_t st = sb + (i % 3) * G_STAGE;
        HG2_STAGE_BODY(st)
    }
    __syncthreads();

    if (kind == 2) {
        #pragma unroll
        for (int t = 0; t < 2; t++) {
            int row = bm * 64 + warp_m * 32 + t * 16 + (lane >> 2);
            #pragma unroll
            for (int j = 0; j < 4; j++) {
                int col = lbn * 128 + warp_n * 32 + j * 8 + ((lane & 3) << 1);
                *(uint32_t*)&vf[(size_t)row * C_ + col]       = pack_f16(acc[t][j][0], acc[t][j][1]);
                *(uint32_t*)&vf[(size_t)(row + 8) * C_ + col] = pack_f16(acc[t][j][2], acc[t][j][3]);
            }
        }
    } else {
        float* ft = (float*)smg;
        #pragma unroll
        for (int t = 0; t < 2; t++) {
            int rl0 = warp_m * 32 + t * 16 + (lane >> 2);
            #pragma unroll
            for (int j = 0; j < 4; j++) {
                int cl = warp_n * 32 + j * 8 + ((lane & 3) << 1);
                ft[rl0 * FTS + cl]           = acc[t][j][0];
                ft[rl0 * FTS + cl + 1]       = acc[t][j][1];
                ft[(rl0 + 8) * FTS + cl]     = acc[t][j][2];
                ft[(rl0 + 8) * FTS + cl + 1] = acc[t][j][3];
            }
        }
        __syncthreads();

        const int r  = tid >> 2;
        const int hh = tid & 3;
        const int cb = hh * 16;
        const float* fr = ft + r * FTS;

        float ss = 0.f;
        #pragma unroll
        for (int i2 = 0; i2 < 16; i2++) {
            float a = fr[cb + i2];
            float b = fr[cb + 64 + i2];
            ss += a * a + b * b;
        }
        ss += __shfl_xor_sync(0xffffffffu, ss, 1);
        ss += __shfl_xor_sync(0xffffffffu, ss, 2);
        float rms = rsqrtf(ss * (1.0f / 128.0f) + 1.1920929e-7f);
        if (kind == 0) rms *= 0.088388347648318447f;

        const int grow = bm * 64 + r;
        const int t    = grow & (T_ - 1);
        __half* Of = kind ? kf : qf;
        const size_t rb = (size_t)grow * C_ + lbn * 128;

        #pragma unroll
        for (int i2 = 0; i2 < 16; i2 += 2) {
            int c0 = cb + i2;
            float a0 = fr[c0] * rms,     b0 = fr[c0 + 64] * rms;
            float a1 = fr[c0 + 1] * rms, b1 = fr[c0 + 65] * rms;
            float co0 = cs[t * 64 + c0], si0 = sn[t * 64 + c0];
            float co1 = cs[t * 64 + c0 + 1], si1 = sn[t * 64 + c0 + 1];
            float y10 =  a0 * co0 + b0 * si0;
            float y11 =  a1 * co1 + b1 * si1;
            float y20 = -a0 * si0 + b0 * co0;
            float y21 = -a1 * si1 + b1 * co1;
            *(uint32_t*)&Of[rb + c0]      = pack_f16(y10, y11);
            *(uint32_t*)&Of[rb + c0 + 64] = pack_f16(y20, y21);
        }
    }
}

// ---------------------------------------------------------------------------
// O-projection fp16 GEMM (fp32 out). 64x128 tile, grid (16, 64).
// ---------------------------------------------------------------------------
__global__ __launch_bounds__(256, 3) void hgemm_o(
    const __half* __restrict__ Af, const __half* __restrict__ Bf,
    float* __restrict__ Cc, int Nn, int K)
{
    extern __shared__ __align__(1024) char smg[];
    const int tid = threadIdx.x, lane = tid & 31, wid = tid >> 5;
    const int warp_m = wid & 1;
    const int warp_n = wid >> 1;
    const int bm = blockIdx.y, bn = blockIdx.x;
    const uint32_t sb = (uint32_t)__cvta_generic_to_shared(smg);

    float acc[2][4][4];
    #pragma unroll
    for (int i = 0; i < 2; i++)
        #pragma unroll
        for (int j = 0; j < 4; j++)
            #pragma unroll
            for (int e = 0; e < 4; e++) acc[i][j][e] = 0.f;

    auto issue = [&](int s, int k0) {
        const uint32_t st = sb + s * G_STAGE;
        #pragma unroll
        for (int it = 0; it < 6; it++) {
            int idx = tid + it * 256;
            if (idx < 512) {
                int r = idx >> 3, ch = idx & 7;
                cp16(st + swz128((uint32_t)(r * 128 + ch * 16)),
                     Af + (size_t)(bm * 64 + r) * K + k0 + ch * 8);
            } else {
                int j = idx - 512;
                int r = j >> 3, ch = j & 7;
                cp16(st + G_ASUB + swz128((uint32_t)(r * 128 + ch * 16)),
                     Bf + (size_t)(bn * 128 + r) * K + k0 + ch * 8);
            }
        }
        asm volatile("cp.async.commit_group;");
    };

    const int NS = K / 64;
    issue(0, 0);
    issue(1, 64);

    const int mlane = lane & 15;
    const int aoff  = (lane >> 4) << 3;
    const int nlane = (lane & 7) + ((lane >> 4) << 3);
    const int klBo  = ((lane >> 3) & 1) << 3;

    for (int i = 0; i < NS; i++) {
        if (i == NS - 1) { asm volatile("cp.async.wait_group 0;"); }
        else             { asm volatile("cp.async.wait_group 1;"); }
        __syncthreads();
        if (i + 2 < NS) issue((i + 2) % 3, (i + 2) * 64);

        const uint32_t st = sb + (i % 3) * G_STAGE;
        HG2_STAGE_BODY(st)
    }

    #pragma unroll
    for (int t = 0; t < 2; t++) {
        int row = bm * 64 + warp_m * 32 + t * 16 + (lane >> 2);
        #pragma unroll
        for (int j = 0; j < 4; j++) {
            int col = bn * 128 + warp_n * 32 + j * 8 + ((lane & 3) << 1);
            *(float2*)&Cc[(size_t)row * Nn + col]       = make_float2(acc[t][j][0], acc[t][j][1]);
            *(float2*)&Cc[(size_t)(row + 8) * Nn + col] = make_float2(acc[t][j][2], acc[t][j][3]);
        }
    }
}

// ---------------------------------------------------------------------------
// Tensor-core flash attention (causal), fp16 mma, fp32 softmax/accum.
// 64-row q tiles, 128 threads, 2-stage KV double buffer -> 3 CTAs/SM.
// Q pre-scaled by 1/sqrt(D).
// ---------------------------------------------------------------------------
#define SQ 136
#define FL_STAGE (2*64*SQ)
#define FL_KF 0
#define FL_VF (64*SQ)
#define FLASH_SMEM (2*FL_STAGE*2)        // 69632 bytes -> 3 CTAs/SM

__global__ __launch_bounds__(128, 3) void flash_f16(
    const __half* __restrict__ qf, const __half* __restrict__ kf,
    const __half* __restrict__ vf, __half* __restrict__ of)
{
    extern __shared__ __half smf[];
    const int tid = threadIdx.x, lane = tid & 31, wid = tid >> 5;
    const int qb = gridDim.x - 1 - blockIdx.x;
    const int b  = blockIdx.y >> 4, h = blockIdx.y & 15;
    const uint32_t sb = (uint32_t)__cvta_generic_to_shared(smf);
    const size_t rowQ = (size_t)b * T_ + (size_t)qb * 64;
    const int colH = h * D_;

    const int wq = wid * 16;
    const int gq0 = qb * 64 + wq;
    const int mlane = lane & 15;
    const int aoff  = (lane >> 4) << 3;
    const int nlane = (lane & 7) + ((lane >> 4) << 3);
    const int klB   = ((lane >> 3) & 1) << 3;

    // ---- stage Q (64 rows), extract fragments ----
    #pragma unroll
    for (int it = 0; it < 8; it++) {
        int idx = tid + it * 128;
        int r = idx >> 4, c = (idx & 15) << 3;
        cp16(sb + 2u * (uint32_t)(r * SQ + c), qf + (rowQ + r) * C_ + colH + c);
    }
    asm volatile("cp.async.commit_group;");
    asm volatile("cp.async.wait_group 0;");
    __syncthreads();

    uint32_t qr[8][4];
    #pragma unroll
    for (int c = 0; c < 8; c++) {
        uint32_t ad = sb + 2u * (uint32_t)((wq + mlane) * SQ + c * 16 + aoff);
        ldmx4(qr[c][0], qr[c][1], qr[c][2], qr[c][3], ad);
    }
    __syncthreads();

    uint32_t kbase[4], vbase[4];
    {
        const int vrow = ((lane >> 3) & 1) * 8 + (lane & 7);
        const int vcol = (lane >> 4) << 3;
        #pragma unroll
        for (int jt = 0; jt < 4; jt++)
            kbase[jt] = 2u * (uint32_t)(FL_KF + (jt * 16 + nlane) * SQ + klB);
        #pragma unroll
        for (int c = 0; c < 4; c++)
            vbase[c] = 2u * (uint32_t)(FL_VF + (c * 16 + vrow) * SQ + vcol);
    }

    auto issueKV = [&](int s, int kt) {
        uint32_t st = s * FL_STAGE;
        #pragma unroll
        for (int it = 0; it < 16; it++) {
            int idx = tid + it * 128;
            int sub = idx >> 10;
            int cid = idx & 1023;
            int r = cid >> 4, c = (cid & 15) << 3;
            size_t g = ((size_t)b * T_ + (size_t)kt * 64 + r) * C_ + colH + c;
            cp16(sb + 2u * (uint32_t)(st + (sub ? FL_VF : FL_KF) + r * SQ + c),
                 (sub ? vf : kf) + g);
        }
        asm volatile("cp.async.commit_group;");
    };

    const int nkt = qb + 1;
    issueKV(0, 0);

    float m0 = -CUDART_INF_F, m1 = -CUDART_INF_F, l0 = 0.f, l1 = 0.f;
    float oacc[16][4];
    #pragma unroll
    for (int j = 0; j < 16; j++)
        #pragma unroll
        for (int e = 0; e < 4; e++) oacc[j][e] = 0.f;

    for (int kt = 0; kt < nkt; kt++) {
        asm volatile("cp.async.wait_group 0;");   // tile kt complete (only pending group)
        __syncthreads();                          // all warps done with buffer (kt+1)&1
        if (kt + 1 < nkt) issueKV((kt + 1) & 1, kt + 1);

        const int kb = kt * 64;
        const uint32_t stB = sb + 2u * (uint32_t)((kt & 1) * FL_STAGE);

        // ---- S = Q K^T (Q pre-scaled) ----
        float sacc[8][4];
        #pragma unroll
        for (int j = 0; j < 8; j++)
            #pragma unroll
            for (int e = 0; e < 4; e++) sacc[j][e] = 0.f;

        #pragma unroll
        for (int c = 0; c < 8; c++) {
            uint32_t bkv[8][2];
            #pragma unroll
            for (int jt = 0; jt < 4; jt++) {
                ldmx4(bkv[2*jt][0], bkv[2*jt][1], bkv[2*jt+1][0], bkv[2*jt+1][1],
                      stB + kbase[jt] + 2u * (uint32_t)(c * 16));
            }
            #pragma unroll
            for (int j = 0; j < 8; j++) mmah16(sacc[j], qr[c], bkv[j]);
        }

        // ---- mask + online softmax ----
        const bool diag = (kb + 63 > gq0);
        const int r0 = gq0 + (lane >> 2), r1 = r0 + 8;
        float tm0 = -CUDART_INF_F, tm1 = -CUDART_INF_F;
        #pragma unroll
        for (int j = 0; j < 8; j++) {
            if (diag) {
                int cc = kb + j * 8 + ((lane & 3) << 1);
                if (cc     > r0) sacc[j][0] = -CUDART_INF_F;
                if (cc + 1 > r0) sacc[j][1] = -CUDART_INF_F;
                if (cc     > r1) sacc[j][2] = -CUDART_INF_F;
                if (cc + 1 > r1) sacc[j][3] = -CUDART_INF_F;
            }
            tm0 = fmaxf(tm0, fmaxf(sacc[j][0], sacc[j][1]));
            tm1 = fmaxf(tm1, fmaxf(sacc[j][2], sacc[j][3]));
        }
        tm0 = fmaxf(tm0, __shfl_xor_sync(0xffffffffu, tm0, 1));
        tm0 = fmaxf(tm0, __shfl_xor_sync(0xffffffffu, tm0, 2));
        tm1 = fmaxf(tm1, __shfl_xor_sync(0xffffffffu, tm1, 1));
        tm1 = fmaxf(tm1, __shfl_xor_sync(0xffffffffu, tm1, 2));
        float mn0 = fmaxf(m0, tm0), mn1 = fmaxf(m1, tm1);
        float a0 = __expf(m0 - mn0), a1 = __expf(m1 - mn1);
        float rs0 = 0.f, rs1 = 0.f;
        #pragma unroll
        for (int j = 0; j < 8; j++) {
            float p0 = __expf(sacc[j][0] - mn0);
            float p1 = __expf(sacc[j][1] - mn0);
            float p2 = __expf(sacc[j][2] - mn1);
            float p3 = __expf(sacc[j][3] - mn1);
            sacc[j][0] = p0; sacc[j][1] = p1; sacc[j][2] = p2; sacc[j][3] = p3;
            rs0 += p0 + p1; rs1 += p2 + p3;
        }
        rs0 += __shfl_xor_sync(0xffffffffu, rs0, 1);
        rs0 += __shfl_xor_sync(0xffffffffu, rs0, 2);
        rs1 += __shfl_xor_sync(0xffffffffu, rs1, 1);
        rs1 += __shfl_xor_sync(0xffffffffu, rs1, 2);
        l0 = l0 * a0 + rs0; l1 = l1 * a1 + rs1;
        m0 = mn0; m1 = mn1;
        #pragma unroll
        for (int j = 0; j < 16; j++) {
            oacc[j][0] *= a0; oacc[j][1] *= a0;
            oacc[j][2] *= a1; oacc[j][3] *= a1;
        }

        uint32_t pf[4][4];
        #pragma unroll
        for (int c = 0; c < 4; c++) {
            pf[c][0] = pack_f16(sacc[2*c][0],   sacc[2*c][1]);
            pf[c][1] = pack_f16(sacc[2*c][2],   sacc[2*c][3]);
            pf[c][2] = pack_f16(sacc[2*c+1][0], sacc[2*c+1][1]);
            pf[c][3] = pack_f16(sacc[2*c+1][2], sacc[2*c+1][3]);
        }

        // ---- O += P V ----
        #pragma unroll
        for (int c = 0; c < 4; c++) {
            #pragma unroll
            for (int dt = 0; dt < 8; dt++) {
                uint32_t bv[4];
                ldmx4t(bv[0], bv[1], bv[2], bv[3],
                       stB + vbase[c] + 2u * (uint32_t)(dt * 16));
                mmah16(oacc[2*dt],   pf[c], bv);
                mmah16(oacc[2*dt+1], pf[c], bv + 2);
            }
        }
    }

    float inv0 = 1.0f / l0, inv1 = 1.0f / l1;
    size_t grow0 = (rowQ + wq + (lane >> 2)) * C_;
    size_t grow1 = grow0 + 8 * C_;
    #pragma unroll
    for (int j = 0; j < 16; j++) {
        int col = colH + j * 8 + ((lane & 3) << 1);
        *(uint32_t*)&of[grow0 + col] = pack_f16(oacc[j][0] * inv0, oacc[j][1] * inv0);
        *(uint32_t*)&of[grow1 + col] = pack_f16(oacc[j][2] * inv1, oacc[j][3] * inv1);
    }
}

// ---------------------------------------------------------------------------
extern "C" void kernel_launch(void* const* d_in, const int* in_sizes, int n_in,
                              void* d_out, int out_size)
{
    (void)in_sizes; (void)n_in; (void)out_size;
    const float* x  = (const float*)d_in[0];
    const float* cs = (const float*)d_in[1];
    const float* sn = (const float*)d_in[2];
    float* out = (float*)d_out;

    __half *xf, *qf, *kf, *vf, *of, *wf;
    cudaGetSymbolAddress((void**)&xf, g_xf);
    cudaGetSymbolAddress((void**)&qf, g_qf);
    cudaGetSymbolAddress((void**)&kf, g_kf);
    cudaGetSymbolAddress((void**)&vf, g_vf);
    cudaGetSymbolAddress((void**)&of, g_of);
    cudaGetSymbolAddress((void**)&wf, g_wf);

    cudaFuncSetAttribute(qkv_gemm, cudaFuncAttributeMaxDynamicSharedMemorySize, G_SMEM);
    cudaFuncSetAttribute(hgemm_o,  cudaFuncAttributeMaxDynamicSharedMemorySize, G_SMEM);
    cudaFuncSetAttribute(flash_f16, cudaFuncAttributeMaxDynamicSharedMemorySize, FLASH_SMEM);

    split_all<<<NTOT4 / (512 * 4), 512>>>((const float4*)x,
        (const float4*)d_in[3], (const float4*)d_in[4],
        (const float4*)d_in[5], (const float4*)d_in[6],
        (uint2*)xf, (uint2*)wf);

    qkv_gemm<<<dim3(48, 64), 256, G_SMEM>>>(xf, wf, cs, sn, qf, kf, vf);

    flash_f16<<<dim3(T_/64, B_*H_), 128, FLASH_SMEM>>>(qf, kf, vf, of);

    hgemm_o<<<dim3(16, 64), 256, G_SMEM>>>(of, wf + 3*(size_t)C_*C_, out, C_, C_);
}